// round 16
// baseline (speedup 1.0000x reference)
#include <cuda_runtime.h>
#include <cuda_bf16.h>
#include <cstdint>

#define CO   256
#define CI   2048
#define HW   1024
#define NB   8
#define NTILES 256

__device__ unsigned int   g_amax = 0u;
__device__ unsigned int   g_tile_ctr = 0u;
__device__ __nv_bfloat16  g_wq[CO * CI];
__device__ float          g_scale[CO];
__device__ float          g_bq[CO];

__device__ __forceinline__ uint32_t smem_u32(const void* p) {
    return static_cast<uint32_t>(__cvta_generic_to_shared(p));
}

// ---- amax: full 64MB scan, MLP=8, sign-strip on ALU pipe ----
// 1024 blocks x 512 threads x 8 uint4 = 4,194,304 uint4 = all 16.7M floats
__global__ __launch_bounds__(512, 2) void amax_kernel(const float* __restrict__ x) {
    const uint4* x4 = reinterpret_cast<const uint4*>(x);
    const int    i0 = blockIdx.x * blockDim.x + threadIdx.x;
    const int    stride = 1024 * 512;

    uint4 v[8];
    #pragma unroll
    for (int j = 0; j < 8; j++) v[j] = x4[i0 + j * stride];

    uint32_t m = 0;
    #pragma unroll
    for (int j = 0; j < 8; j++) {
        m = max(m, v[j].x & 0x7fffffffu);
        m = max(m, v[j].y & 0x7fffffffu);
        m = max(m, v[j].z & 0x7fffffffu);
        m = max(m, v[j].w & 0x7fffffffu);
    }
    // non-negative float bits compare like uints
    #pragma unroll
    for (int o = 16; o; o >>= 1) m = max(m, __shfl_xor_sync(0xffffffffu, m, o));
    __shared__ uint32_t red[16];
    if ((threadIdx.x & 31) == 0) red[threadIdx.x >> 5] = m;
    __syncthreads();
    if (threadIdx.x < 16) {
        m = red[threadIdx.x];
        #pragma unroll
        for (int o = 8; o; o >>= 1) m = max(m, __shfl_xor_sync(0xffffu, m, o));
        if (threadIdx.x == 0) atomicMax(&g_amax, m);
    }
}

__global__ void wprep_kernel(const float* __restrict__ w, const float* __restrict__ bias) {
    const int co  = blockIdx.x;
    const int tid = threadIdx.x;
    if (co == 0 && tid == 0) g_tile_ctr = 0u;    // reset tile queue for this launch/replay
    const float* wr = w + (size_t)co * CI;
    float vals[8];
    float m = 0.f;
    #pragma unroll
    for (int j = 0; j < 8; j++) {
        vals[j] = wr[tid + 256 * j];
        m = fmaxf(m, fabsf(vals[j]));
    }
    #pragma unroll
    for (int o = 16; o; o >>= 1) m = fmaxf(m, __shfl_xor_sync(0xffffffffu, m, o));
    __shared__ float red[8];
    __shared__ float s_sw_sh;
    if ((tid & 31) == 0) red[tid >> 5] = m;
    __syncthreads();
    if (tid == 0) {
        float mm = red[0];
        #pragma unroll
        for (int i = 1; i < 8; i++) mm = fmaxf(mm, red[i]);
        float s_w = fmaxf(mm, 1e-8f) / 127.f;
        s_sw_sh = s_w;
        float s_a = fmaxf(__uint_as_float(g_amax), 1e-8f) / 127.f;
        float s_b = s_a * s_w;
        g_scale[co] = s_b;
        g_bq[co]    = rintf(bias[co] / s_b) * s_b;
    }
    __syncthreads();
    const float s_w = s_sw_sh;
    #pragma unroll
    for (int j = 0; j < 8; j++) {
        float q = fminf(fmaxf(rintf(vals[j] / s_w), -128.f), 127.f);
        g_wq[(size_t)co * CI + tid + 256 * j] = __float2bfloat16(q);
    }
}

// ---- GEMM: persistent CTAs + tile queue; per-tile body = R2 (BM=128,BN=64,BK=32) ----
#define BM   128
#define BN   64
#define BK   32
#define KT_N (CI / BK)   // 64
#define ASTR 40          // A smem row stride (bf16 elems)
#define BSTR 72          // B smem row stride (bf16 elems)

__global__ __launch_bounds__(256, 2) void gemm_kernel(const float* __restrict__ x,
                                                      float* __restrict__ out) {
    __shared__ __align__(16) __nv_bfloat16 As[2][BM * ASTR];
    __shared__ __align__(16) __nv_bfloat16 Bs[2][BK * BSTR];
    __shared__ int s_tile;

    const int tid  = threadIdx.x;
    const int lane = tid & 31;
    const int warp = tid >> 5;
    const int wm   = warp >> 1;   // 0..3 -> 32 rows each
    const int wn   = warp & 1;    // 0..1 -> 32 cols each

    const float s_a    = fmaxf(__uint_as_float(g_amax), 1e-8f) / 127.f;
    const float inv_sa = 1.f / s_a;
    const float MAGIC  = 12582912.f;   // 1.5 * 2^23

    const int brow = tid >> 4;          // 0..15, +16
    const int bcol = (tid & 15) * 4;    // 0..60
    const int arow = tid >> 2;          // 0..63, +64
    const int acol = (tid & 3) * 8;     // 0,8,16,24

    for (;;) {
        if (tid == 0) s_tile = (int)atomicAdd(&g_tile_ctr, 1u);
        __syncthreads();
        const int t = s_tile;
        if (t >= NTILES) return;

        const int tileM = t & 1;            // fastest -> both M tiles of same x cols run close
        const int tileN = t >> 1;           // 0..127
        const int b     = tileN >> 4;
        const int hw0   = (tileN & 15) * BN;
        const float* xb = x + (size_t)b * CI * HW + hw0;
        const __nv_bfloat16* wq = g_wq + (size_t)(tileM * BM) * CI;

        float4 bReg[2];

        auto loadB = [&](int kt) {
            const float* xp = xb + (size_t)(kt * BK) * HW;
            bReg[0] = *reinterpret_cast<const float4*>(xp + (size_t)brow * HW + bcol);
            bReg[1] = *reinterpret_cast<const float4*>(xp + (size_t)(brow + 16) * HW + bcol);
        };
        auto storeB = [&](int st) {
            #pragma unroll
            for (int i = 0; i < 2; i++) {
                float4 v = bReg[i];
                float q0 = fmaf(v.x, inv_sa, MAGIC) - MAGIC;
                float q1 = fmaf(v.y, inv_sa, MAGIC) - MAGIC;
                float q2 = fmaf(v.z, inv_sa, MAGIC) - MAGIC;
                float q3 = fmaf(v.w, inv_sa, MAGIC) - MAGIC;
                __nv_bfloat162* dst =
                    reinterpret_cast<__nv_bfloat162*>(&Bs[st][(brow + 16 * i) * BSTR + bcol]);
                dst[0] = __floats2bfloat162_rn(q0, q1);
                dst[1] = __floats2bfloat162_rn(q2, q3);
            }
        };
        auto loadA = [&](int kt, int st) {
            const __nv_bfloat16* wp = wq + kt * BK;
            #pragma unroll
            for (int i = 0; i < 2; i++) {
                uint32_t dst = smem_u32(&As[st][(arow + 64 * i) * ASTR + acol]);
                const void* src = wp + (size_t)(arow + 64 * i) * CI + acol;
                asm volatile("cp.async.cg.shared.global [%0], [%1], 16;\n" :: "r"(dst), "l"(src));
            }
            asm volatile("cp.async.commit_group;\n");
        };

        // prologue: stage 0
        loadA(0, 0);
        loadB(0);
        storeB(0);
        asm volatile("cp.async.wait_group 0;\n");
        __syncthreads();

        float acc[2][4][4];
        #pragma unroll
        for (int mt = 0; mt < 2; mt++)
            #pragma unroll
            for (int nt = 0; nt < 4; nt++)
                #pragma unroll
                for (int r = 0; r < 4; r++) acc[mt][nt][r] = 0.f;

        for (int kt = 0; kt < KT_N; kt++) {
            const int cur = kt & 1;
            const int nxt = cur ^ 1;
            if (kt + 1 < KT_N) {
                loadA(kt + 1, nxt);
                loadB(kt + 1);
            }

            #pragma unroll
            for (int kk = 0; kk < 2; kk++) {
                uint32_t a[2][4];
                #pragma unroll
                for (int mt = 0; mt < 2; mt++) {
                    int mr = wm * 32 + mt * 16 + (lane & 15);
                    int kc = kk * 16 + (lane >> 4) * 8;
                    uint32_t addr = smem_u32(&As[cur][mr * ASTR + kc]);
                    asm volatile("ldmatrix.sync.aligned.m8n8.x4.shared.b16 {%0,%1,%2,%3}, [%4];"
                                 : "=r"(a[mt][0]), "=r"(a[mt][1]), "=r"(a[mt][2]), "=r"(a[mt][3])
                                 : "r"(addr));
                }
                uint32_t bf[2][4];
                #pragma unroll
                for (int np = 0; np < 2; np++) {
                    int kr = kk * 16 + (lane & 15);
                    int nc = wn * 32 + np * 16 + (lane >> 4) * 8;
                    uint32_t addr = smem_u32(&Bs[cur][kr * BSTR + nc]);
                    asm volatile("ldmatrix.sync.aligned.m8n8.x4.trans.shared.b16 {%0,%1,%2,%3}, [%4];"
                                 : "=r"(bf[np][0]), "=r"(bf[np][1]), "=r"(bf[np][2]), "=r"(bf[np][3])
                                 : "r"(addr));
                }
                #pragma unroll
                for (int mt = 0; mt < 2; mt++) {
                    #pragma unroll
                    for (int nt = 0; nt < 4; nt++) {
                        uint32_t b0 = bf[nt >> 1][(nt & 1) * 2 + 0];
                        uint32_t b1 = bf[nt >> 1][(nt & 1) * 2 + 1];
                        asm volatile(
                            "mma.sync.aligned.m16n8k16.row.col.f32.bf16.bf16.f32 "
                            "{%0,%1,%2,%3}, {%4,%5,%6,%7}, {%8,%9}, {%0,%1,%2,%3};"
                            : "+f"(acc[mt][nt][0]), "+f"(acc[mt][nt][1]),
                              "+f"(acc[mt][nt][2]), "+f"(acc[mt][nt][3])
                            : "r"(a[mt][0]), "r"(a[mt][1]), "r"(a[mt][2]), "r"(a[mt][3]),
                              "r"(b0), "r"(b1));
                    }
                }
            }

            if (kt + 1 < KT_N) {
                storeB(nxt);
                asm volatile("cp.async.wait_group 0;\n");
            }
            __syncthreads();
        }

        // epilogue (registers + constants only; safe vs next tile's smem writes)
        #pragma unroll
        for (int mt = 0; mt < 2; mt++) {
            int co0 = tileM * BM + wm * 32 + mt * 16 + (lane >> 2);
            float s0 = g_scale[co0],     q0 = g_bq[co0];
            float s1 = g_scale[co0 + 8], q1 = g_bq[co0 + 8];
            #pragma unroll
            for (int nt = 0; nt < 4; nt++) {
                int hw = hw0 + wn * 32 + nt * 8 + (lane & 3) * 2;
                float* o = out + (size_t)b * CO * HW + (size_t)co0 * HW + hw;
                float2 v0 = make_float2(acc[mt][nt][0] * s0 + q0, acc[mt][nt][1] * s0 + q0);
                float2 v1 = make_float2(acc[mt][nt][2] * s1 + q1, acc[mt][nt][3] * s1 + q1);
                *reinterpret_cast<float2*>(o) = v0;
                *reinterpret_cast<float2*>(o + 8 * HW) = v1;
            }
        }
        __syncthreads();   // all done with this tile before s_tile is overwritten
    }
}

extern "C" void kernel_launch(void* const* d_in, const int* in_sizes, int n_in,
                              void* d_out, int out_size) {
    const float* x    = (const float*)d_in[0];
    const float* w    = (const float*)d_in[1];
    const float* bias = (const float*)d_in[2];
    float* out        = (float*)d_out;

    amax_kernel<<<1024, 512>>>(x);
    wprep_kernel<<<CO, 256>>>(w, bias);
    gemm_kernel<<<296, 256>>>(x, out);   // 2 CTAs/SM on 148 SMs, tile queue of 256
}

// round 17
// speedup vs baseline: 1.0173x; 1.0173x over previous
#include <cuda_runtime.h>
#include <cuda_bf16.h>
#include <cstdint>

#define CO   256
#define CI   2048
#define HW   1024
#define NB   8
#define NTILES 256

#define AMAX_BLKS 2048

__device__ unsigned int   g_amax = 0u;
__device__ unsigned int   g_tile_ctr = 0u;
__device__ __nv_bfloat16  g_wq[CO * CI];
__device__ float          g_sw[CO];      // per-channel weight scale

__device__ __forceinline__ uint32_t smem_u32(const void* p) {
    return static_cast<uint32_t>(__cvta_generic_to_shared(p));
}

// ---- fused prep: blocks [0,256) quantize weights; blocks [256, 256+AMAX_BLKS) scan x ----
__global__ __launch_bounds__(512, 2) void prep_kernel(const float* __restrict__ x,
                                                      const float* __restrict__ w) {
    const int tid = threadIdx.x;

    if (blockIdx.x < CO) {
        // ---------- weight quant for channel co (independent of amax) ----------
        const int co = blockIdx.x;
        if (co == 0 && tid == 0) g_tile_ctr = 0u;   // reset gemm tile queue per replay
        const float* wr = w + (size_t)co * CI;
        float4 v = *reinterpret_cast<const float4*>(wr + tid * 4);
        float m = fmaxf(fmaxf(fabsf(v.x), fabsf(v.y)), fmaxf(fabsf(v.z), fabsf(v.w)));
        #pragma unroll
        for (int o = 16; o; o >>= 1) m = fmaxf(m, __shfl_xor_sync(0xffffffffu, m, o));
        __shared__ float red[16];
        __shared__ float s_sw_sh;
        if ((tid & 31) == 0) red[tid >> 5] = m;
        __syncthreads();
        if (tid == 0) {
            float mm = red[0];
            #pragma unroll
            for (int i = 1; i < 16; i++) mm = fmaxf(mm, red[i]);
            float s_w = fmaxf(mm, 1e-8f) / 127.f;
            s_sw_sh = s_w;
            g_sw[co] = s_w;
        }
        __syncthreads();
        const float inv_sw = 1.f / s_sw_sh;
        float q0 = fminf(fmaxf(rintf(v.x * inv_sw), -128.f), 127.f);
        float q1 = fminf(fmaxf(rintf(v.y * inv_sw), -128.f), 127.f);
        float q2 = fminf(fmaxf(rintf(v.z * inv_sw), -128.f), 127.f);
        float q3 = fminf(fmaxf(rintf(v.w * inv_sw), -128.f), 127.f);
        __nv_bfloat162 p0 = __floats2bfloat162_rn(q0, q1);
        __nv_bfloat162 p1 = __floats2bfloat162_rn(q2, q3);
        uint2 pk = make_uint2(*reinterpret_cast<uint32_t*>(&p0),
                              *reinterpret_cast<uint32_t*>(&p1));
        *reinterpret_cast<uint2*>(g_wq + (size_t)co * CI + tid * 4) = pk;
        return;
    }

    // ---------- amax over x: AMAX_BLKS blocks x 512 thr x 4 uint4 = full 4M uint4 ----------
    const uint4* x4 = reinterpret_cast<const uint4*>(x);
    const int bid   = blockIdx.x - CO;
    const int i0    = bid * 512 + tid;
    const int strd  = AMAX_BLKS * 512;

    uint4 v[4];
    #pragma unroll
    for (int j = 0; j < 4; j++) v[j] = x4[i0 + j * strd];

    uint32_t m = 0;
    #pragma unroll
    for (int j = 0; j < 4; j++) {
        m = max(m, v[j].x & 0x7fffffffu);
        m = max(m, v[j].y & 0x7fffffffu);
        m = max(m, v[j].z & 0x7fffffffu);
        m = max(m, v[j].w & 0x7fffffffu);
    }
    #pragma unroll
    for (int o = 16; o; o >>= 1) m = max(m, __shfl_xor_sync(0xffffffffu, m, o));
    __shared__ uint32_t redu[16];
    if ((tid & 31) == 0) redu[tid >> 5] = m;
    __syncthreads();
    if (tid < 16) {
        m = redu[tid];
        #pragma unroll
        for (int o = 8; o; o >>= 1) m = max(m, __shfl_xor_sync(0xffffu, m, o));
        if (tid == 0) atomicMax(&g_amax, m);
    }
}

// ---- GEMM: persistent CTAs + tile queue; per-tile body = R2 (BM=128,BN=64,BK=32) ----
#define BM   128
#define BN   64
#define BK   32
#define KT_N (CI / BK)   // 64
#define ASTR 40          // A smem row stride (bf16 elems)
#define BSTR 72          // B smem row stride (bf16 elems)

__global__ __launch_bounds__(256, 2) void gemm_kernel(const float* __restrict__ x,
                                                      const float* __restrict__ bias,
                                                      float* __restrict__ out) {
    __shared__ __align__(16) __nv_bfloat16 As[2][BM * ASTR];
    __shared__ __align__(16) __nv_bfloat16 Bs[2][BK * BSTR];
    __shared__ int s_tile;

    const int tid  = threadIdx.x;
    const int lane = tid & 31;
    const int warp = tid >> 5;
    const int wm   = warp >> 1;   // 0..3 -> 32 rows each
    const int wn   = warp & 1;    // 0..1 -> 32 cols each

    const float s_a    = fmaxf(__uint_as_float(g_amax), 1e-8f) / 127.f;
    const float inv_sa = 1.f / s_a;
    const float MAGIC  = 12582912.f;   // 1.5 * 2^23

    const int brow = tid >> 4;          // 0..15, +16
    const int bcol = (tid & 15) * 4;    // 0..60
    const int arow = tid >> 2;          // 0..63, +64
    const int acol = (tid & 3) * 8;     // 0,8,16,24

    for (;;) {
        if (tid == 0) s_tile = (int)atomicAdd(&g_tile_ctr, 1u);
        __syncthreads();
        const int t = s_tile;
        if (t >= NTILES) return;

        const int tileM = t & 1;
        const int tileN = t >> 1;           // 0..127
        const int b     = tileN >> 4;
        const int hw0   = (tileN & 15) * BN;
        const float* xb = x + (size_t)b * CI * HW + hw0;
        const __nv_bfloat16* wq = g_wq + (size_t)(tileM * BM) * CI;

        float4 bReg[2];

        auto loadB = [&](int kt) {
            const float* xp = xb + (size_t)(kt * BK) * HW;
            bReg[0] = *reinterpret_cast<const float4*>(xp + (size_t)brow * HW + bcol);
            bReg[1] = *reinterpret_cast<const float4*>(xp + (size_t)(brow + 16) * HW + bcol);
        };
        auto storeB = [&](int st) {
            #pragma unroll
            for (int i = 0; i < 2; i++) {
                float4 v = bReg[i];
                float q0 = fmaf(v.x, inv_sa, MAGIC) - MAGIC;
                float q1 = fmaf(v.y, inv_sa, MAGIC) - MAGIC;
                float q2 = fmaf(v.z, inv_sa, MAGIC) - MAGIC;
                float q3 = fmaf(v.w, inv_sa, MAGIC) - MAGIC;
                __nv_bfloat162* dst =
                    reinterpret_cast<__nv_bfloat162*>(&Bs[st][(brow + 16 * i) * BSTR + bcol]);
                dst[0] = __floats2bfloat162_rn(q0, q1);
                dst[1] = __floats2bfloat162_rn(q2, q3);
            }
        };
        auto loadA = [&](int kt, int st) {
            const __nv_bfloat16* wp = wq + kt * BK;
            #pragma unroll
            for (int i = 0; i < 2; i++) {
                uint32_t dst = smem_u32(&As[st][(arow + 64 * i) * ASTR + acol]);
                const void* src = wp + (size_t)(arow + 64 * i) * CI + acol;
                asm volatile("cp.async.cg.shared.global [%0], [%1], 16;\n" :: "r"(dst), "l"(src));
            }
            asm volatile("cp.async.commit_group;\n");
        };

        loadA(0, 0);
        loadB(0);
        storeB(0);
        asm volatile("cp.async.wait_group 0;\n");
        __syncthreads();

        float acc[2][4][4];
        #pragma unroll
        for (int mt = 0; mt < 2; mt++)
            #pragma unroll
            for (int nt = 0; nt < 4; nt++)
                #pragma unroll
                for (int r = 0; r < 4; r++) acc[mt][nt][r] = 0.f;

        for (int kt = 0; kt < KT_N; kt++) {
            const int cur = kt & 1;
            const int nxt = cur ^ 1;
            if (kt + 1 < KT_N) {
                loadA(kt + 1, nxt);
                loadB(kt + 1);
            }

            #pragma unroll
            for (int kk = 0; kk < 2; kk++) {
                uint32_t a[2][4];
                #pragma unroll
                for (int mt = 0; mt < 2; mt++) {
                    int mr = wm * 32 + mt * 16 + (lane & 15);
                    int kc = kk * 16 + (lane >> 4) * 8;
                    uint32_t addr = smem_u32(&As[cur][mr * ASTR + kc]);
                    asm volatile("ldmatrix.sync.aligned.m8n8.x4.shared.b16 {%0,%1,%2,%3}, [%4];"
                                 : "=r"(a[mt][0]), "=r"(a[mt][1]), "=r"(a[mt][2]), "=r"(a[mt][3])
                                 : "r"(addr));
                }
                uint32_t bf[2][4];
                #pragma unroll
                for (int np = 0; np < 2; np++) {
                    int kr = kk * 16 + (lane & 15);
                    int nc = wn * 32 + np * 16 + (lane >> 4) * 8;
                    uint32_t addr = smem_u32(&Bs[cur][kr * BSTR + nc]);
                    asm volatile("ldmatrix.sync.aligned.m8n8.x4.trans.shared.b16 {%0,%1,%2,%3}, [%4];"
                                 : "=r"(bf[np][0]), "=r"(bf[np][1]), "=r"(bf[np][2]), "=r"(bf[np][3])
                                 : "r"(addr));
                }
                #pragma unroll
                for (int mt = 0; mt < 2; mt++) {
                    #pragma unroll
                    for (int nt = 0; nt < 4; nt++) {
                        uint32_t b0 = bf[nt >> 1][(nt & 1) * 2 + 0];
                        uint32_t b1 = bf[nt >> 1][(nt & 1) * 2 + 1];
                        asm volatile(
                            "mma.sync.aligned.m16n8k16.row.col.f32.bf16.bf16.f32 "
                            "{%0,%1,%2,%3}, {%4,%5,%6,%7}, {%8,%9}, {%0,%1,%2,%3};"
                            : "+f"(acc[mt][nt][0]), "+f"(acc[mt][nt][1]),
                              "+f"(acc[mt][nt][2]), "+f"(acc[mt][nt][3])
                            : "r"(a[mt][0]), "r"(a[mt][1]), "r"(a[mt][2]), "r"(a[mt][3]),
                              "r"(b0), "r"(b1));
                    }
                }
            }

            if (kt + 1 < KT_N) {
                storeB(nxt);
                asm volatile("cp.async.wait_group 0;\n");
            }
            __syncthreads();
        }

        // epilogue: s_b = s_a * s_w[co]; b_q = rint(bias/s_b)*s_b computed here
        #pragma unroll
        for (int mt = 0; mt < 2; mt++) {
            int co0 = tileM * BM + wm * 32 + mt * 16 + (lane >> 2);
            float s0 = s_a * g_sw[co0];
            float s1 = s_a * g_sw[co0 + 8];
            float q0 = rintf(bias[co0] / s0) * s0;
            float q1 = rintf(bias[co0 + 8] / s1) * s1;
            #pragma unroll
            for (int nt = 0; nt < 4; nt++) {
                int hw = hw0 + wn * 32 + nt * 8 + (lane & 3) * 2;
                float* o = out + (size_t)b * CO * HW + (size_t)co0 * HW + hw;
                float2 v0 = make_float2(acc[mt][nt][0] * s0 + q0, acc[mt][nt][1] * s0 + q0);
                float2 v1 = make_float2(acc[mt][nt][2] * s1 + q1, acc[mt][nt][3] * s1 + q1);
                *reinterpret_cast<float2*>(o) = v0;
                *reinterpret_cast<float2*>(o + 8 * HW) = v1;
            }
        }
        __syncthreads();
    }
}

extern "C" void kernel_launch(void* const* d_in, const int* in_sizes, int n_in,
                              void* d_out, int out_size) {
    const float* x    = (const float*)d_in[0];
    const float* w    = (const float*)d_in[1];
    const float* bias = (const float*)d_in[2];
    float* out        = (float*)d_out;

    prep_kernel<<<CO + AMAX_BLKS, 512>>>(x, w);
    gemm_kernel<<<296, 256>>>(x, bias, out);
}